// round 6
// baseline (speedup 1.0000x reference)
#include <cuda_runtime.h>
#include <cstdint>

#define NPTS  8192
#define BATCH 2
#define KNN   30
#define ROWS_PER_BLOCK 16
#define NTHREADS (ROWS_PER_BLOCK * 32)
#define MAXF 3.4028234663852886e38f
#define SMEM_BYTES (NPTS * 16 + (NPTS / 32) * 4)

// Scratch (no cudaMalloc allowed): packed points (x,y,z,|x|^2) and validity bitmask.
__device__ float4   g_pts[BATCH * NPTS];
__device__ unsigned g_msk[BATCH * NPTS / 32];

__global__ void prep_kernel(const float* __restrict__ X, const int* __restrict__ C) {
    int p = blockIdx.x * blockDim.x + threadIdx.x;   // grid sized exactly
    float x = X[p * 3 + 0], y = X[p * 3 + 1], z = X[p * 3 + 2];
    // XLA GPU row-reduce (warp shfl-down butterfly over a 3-element row):
    // lane0 accumulates v0 (+0s) + v2 + v1  =>  x2 = rn(rn(x^2 + z^2) + y^2)
    float x2 = __fadd_rn(__fadd_rn(__fmul_rn(x, x), __fmul_rn(z, z)), __fmul_rn(y, y));
    g_pts[p] = make_float4(x, y, z, x2);
    unsigned bit = (C[p] > 0) ? 1u : 0u;             // C is int32 (jax x64 disabled)
    unsigned word = __ballot_sync(0xffffffffu, bit);
    if ((threadIdx.x & 31) == 0) g_msk[p >> 5] = word;
}

extern __shared__ unsigned char smem_raw[];

__global__ void __launch_bounds__(NTHREADS) knn_kernel(float* __restrict__ out) {
    float4*   spts = (float4*)smem_raw;
    unsigned* smsk = (unsigned*)(smem_raw + NPTS * sizeof(float4));

    const int warp = threadIdx.x >> 5;
    const int lane = threadIdx.x & 31;
    const int r = blockIdx.x * ROWS_PER_BLOCK + warp;   // global row
    const int b = r >> 13;                              // r / 8192
    const int i = r & (NPTS - 1);

    const float4*   gp = g_pts + b * NPTS;
    const unsigned* gm = g_msk + b * (NPTS / 32);
    for (int t = threadIdx.x; t < NPTS; t += NTHREADS) spts[t] = gp[t];
    for (int t = threadIdx.x; t < NPTS / 32; t += NTHREADS) smsk[t] = gm[t];
    __syncthreads();

    float* outIdx = out + (size_t)r * KNN;
    float* outMsk = out + (size_t)(BATCH * NPTS) * KNN + (size_t)r * KNN;

    const float4 pi = spts[i];
    const unsigned mi = (smsk[i >> 5] >> (i & 31)) & 1u;

    if (!mi) {
        // Fully-masked row: D_masked is constant MAX -> stable top_k gives 0..29, mask 0.
        if (lane < KNN) { outIdx[lane] = (float)lane; outMsk[lane] = 0.0f; }
        return;
    }

    // Warp-cooperative sorted top-32 list (we use first 30). Lane l holds rank l.
    float lv  = __int_as_float(0x7f800000);  // +inf sentinel
    int   li  = 0x7fffffff;
    float v29 = lv;                          // current 30th-best key
    int   i29 = li;
    float thr2 = lv;                         // conservative d^2 pre-filter

    #pragma unroll 4
    for (int t = 0; t < NPTS / 32; t++) {
        const int j = t * 32 + lane;
        const float4 pj = spts[j];
        // s = x2_i + x2_j  (one rounding)
        const float s   = __fadd_rn(pi.w, pj.w);
        // dot: cuBLAS SGEMM ascending-k FFMA chain, acc starts at 0
        const float dot = fmaf(pi.z, pj.z, fmaf(pi.y, pj.y, __fmul_rn(pi.x, pj.x)));
        // D2 = s - 2*dot  (2*dot exact; single rounded subtract)
        const float d2  = __fsub_rn(s, __fmul_rn(2.0f, dot));
        const unsigned mw = smsk[t];
        const bool mbit = (mw >> lane) & 1u;

        float Dc = MAXF;
        bool pass;
        if (mbit) {
            if (d2 < thr2) {
                Dc = __fsqrt_rn(fmaxf(d2, 0.0f));   // IEEE sqrt regardless of fast-math
                pass = (Dc < v29) || (Dc == v29 && j < i29);
            } else {
                pass = false;
            }
        } else {
            // masked candidate has key MAX_FLOAT32 (tie-broken by index)
            pass = (MAXF < v29) || (v29 == MAXF && j < i29);
        }

        unsigned act = __ballot_sync(0xffffffffu, pass);
        while (act) {
            const int src = __ffs(act) - 1;
            act &= act - 1;
            const float cd = __shfl_sync(0xffffffffu, Dc, src);
            const int   cj = t * 32 + src;
            // recheck against (possibly tightened) threshold — warp-uniform condition
            if (cd < v29 || (cd == v29 && cj < i29)) {
                const bool less = (lv < cd) || (lv == cd && li < cj);
                const int  p    = __popc(__ballot_sync(0xffffffffu, less));
                const float upv = __shfl_up_sync(0xffffffffu, lv, 1);
                const int   upi = __shfl_up_sync(0xffffffffu, li, 1);
                if (lane == p)      { lv = cd;  li = cj;  }
                else if (lane > p)  { lv = upv; li = upi; }
                v29 = __shfl_sync(0xffffffffu, lv, 29);
                i29 = __shfl_sync(0xffffffffu, li, 29);
                thr2 = __fmul_rn(__fmul_rn(v29, v29), 1.00002f);   // inf-safe margin
            }
        }
    }

    if (lane < KNN) {
        outIdx[lane] = (float)li;
        const unsigned mj = (smsk[li >> 5] >> (li & 31)) & 1u;
        outMsk[lane] = mj ? 1.0f : 0.0f;   // mi == 1 on this path
    }
}

extern "C" void kernel_launch(void* const* d_in, const int* in_sizes, int n_in,
                              void* d_out, int out_size) {
    // Defensive input-order resolution: X has BATCH*NPTS*3 = 49152 elements, C has 16384.
    int xi = 0, ci = 1;
    if (in_sizes[0] == BATCH * NPTS) { xi = 1; ci = 0; }
    const float* X = (const float*)d_in[xi];
    const int*   C = (const int*)d_in[ci];
    float* out = (float*)d_out;

    prep_kernel<<<(BATCH * NPTS) / 256, 256>>>(X, C);

    cudaFuncSetAttribute(knn_kernel, cudaFuncAttributeMaxDynamicSharedMemorySize, SMEM_BYTES);
    knn_kernel<<<(BATCH * NPTS) / ROWS_PER_BLOCK, NTHREADS, SMEM_BYTES>>>(out);
}

// round 7
// speedup vs baseline: 2.3690x; 2.3690x over previous
#include <cuda_runtime.h>
#include <cstdint>

#define NPTS  8192
#define BATCH 2
#define KNN   30
#define ROWS_PER_BLOCK 32
#define NTHREADS (ROWS_PER_BLOCK * 32)
#define MAXF 3.4028234663852886e38f
#define SMEM_BYTES (NPTS * 16 + (NPTS / 32) * 4)

// Scratch (no cudaMalloc allowed): packed points (x,y,z,|x|^2) and validity bitmask.
__device__ float4   g_pts[BATCH * NPTS];
__device__ unsigned g_msk[BATCH * NPTS / 32];

__global__ void prep_kernel(const float* __restrict__ X, const int* __restrict__ C) {
    int p = blockIdx.x * blockDim.x + threadIdx.x;   // grid sized exactly
    float x = X[p * 3 + 0], y = X[p * 3 + 1], z = X[p * 3 + 2];
    // XLA GPU row-reduce (warp shfl-down butterfly over a 3-element row):
    // lane0 accumulates v0 (+0s) + v2 + v1  =>  x2 = rn(rn(x^2 + z^2) + y^2)
    float x2 = __fadd_rn(__fadd_rn(__fmul_rn(x, x), __fmul_rn(z, z)), __fmul_rn(y, y));
    g_pts[p] = make_float4(x, y, z, x2);
    unsigned bit = (C[p] > 0) ? 1u : 0u;             // C is int32 (jax x64 disabled)
    unsigned word = __ballot_sync(0xffffffffu, bit);
    if ((threadIdx.x & 31) == 0) g_msk[p >> 5] = word;
}

extern __shared__ unsigned char smem_raw[];

__global__ void __launch_bounds__(NTHREADS) knn_kernel(float* __restrict__ out) {
    float4*   spts = (float4*)smem_raw;
    unsigned* smsk = (unsigned*)(smem_raw + NPTS * sizeof(float4));

    const int warp = threadIdx.x >> 5;
    const int lane = threadIdx.x & 31;
    const int r = blockIdx.x * ROWS_PER_BLOCK + warp;   // global row
    const int b = r >> 13;                              // r / 8192
    const int i = r & (NPTS - 1);

    const float4*   gp = g_pts + b * NPTS;
    const unsigned* gm = g_msk + b * (NPTS / 32);
    for (int t = threadIdx.x; t < NPTS; t += NTHREADS) spts[t] = gp[t];
    for (int t = threadIdx.x; t < NPTS / 32; t += NTHREADS) smsk[t] = gm[t];
    __syncthreads();

    float* outIdx = out + (size_t)r * KNN;
    float* outMsk = out + (size_t)(BATCH * NPTS) * KNN + (size_t)r * KNN;

    const float4 pi = spts[i];
    const unsigned mi = (smsk[i >> 5] >> (i & 31)) & 1u;

    if (!mi) {
        // Fully-masked row: D_masked is constant MAX -> stable top_k gives 0..29, mask 0.
        if (lane < KNN) { outIdx[lane] = (float)lane; outMsk[lane] = 0.0f; }
        return;
    }

    // Warp-cooperative sorted top-32 list (we use first 30). Lane l holds rank l.
    float lv  = __int_as_float(0x7f800000);  // +inf sentinel
    int   li  = 0x7fffffff;
    float v29 = lv;                          // current 30th-best key
    int   i29 = li;
    float thr2 = lv;                         // conservative d^2 pre-filter

    #pragma unroll 4
    for (int t = 0; t < NPTS / 32; t++) {
        const int j = t * 32 + lane;
        const float4 pj = spts[j];
        // s = x2_i + x2_j  (one rounding)
        const float s   = __fadd_rn(pi.w, pj.w);
        // dot: cuBLAS SGEMM ascending-k FFMA chain, acc starts at 0
        const float dot = fmaf(pi.z, pj.z, fmaf(pi.y, pj.y, __fmul_rn(pi.x, pj.x)));
        // D2 = s - 2*dot  (2*dot exact; single rounded subtract)
        const float d2  = __fsub_rn(s, __fmul_rn(2.0f, dot));
        const unsigned mw = smsk[t];
        const bool mbit = (mw >> lane) & 1u;

        float Dc = MAXF;
        bool pass;
        if (mbit) {
            if (d2 < thr2) {
                Dc = __fsqrt_rn(fmaxf(d2, 0.0f));   // IEEE sqrt regardless of fast-math
                pass = (Dc < v29) || (Dc == v29 && j < i29);
            } else {
                pass = false;
            }
        } else {
            // masked candidate has key MAX_FLOAT32 (tie-broken by index)
            pass = (MAXF < v29) || (v29 == MAXF && j < i29);
        }

        unsigned act = __ballot_sync(0xffffffffu, pass);
        while (act) {
            const int src = __ffs(act) - 1;
            act &= act - 1;
            const float cd = __shfl_sync(0xffffffffu, Dc, src);
            const int   cj = t * 32 + src;
            // recheck against (possibly tightened) threshold — warp-uniform condition
            if (cd < v29 || (cd == v29 && cj < i29)) {
                const bool less = (lv < cd) || (lv == cd && li < cj);
                const int  p    = __popc(__ballot_sync(0xffffffffu, less));
                const float upv = __shfl_up_sync(0xffffffffu, lv, 1);
                const int   upi = __shfl_up_sync(0xffffffffu, li, 1);
                if (lane == p)      { lv = cd;  li = cj;  }
                else if (lane > p)  { lv = upv; li = upi; }
                v29 = __shfl_sync(0xffffffffu, lv, 29);
                i29 = __shfl_sync(0xffffffffu, li, 29);
                thr2 = __fmul_rn(__fmul_rn(v29, v29), 1.00002f);   // inf-safe margin
            }
        }
    }

    if (lane < KNN) {
        outIdx[lane] = (float)li;
        const unsigned mj = (smsk[li >> 5] >> (li & 31)) & 1u;
        outMsk[lane] = mj ? 1.0f : 0.0f;   // mi == 1 on this path
    }
}

extern "C" void kernel_launch(void* const* d_in, const int* in_sizes, int n_in,
                              void* d_out, int out_size) {
    // Defensive input-order resolution: X has BATCH*NPTS*3 = 49152 elements, C has 16384.
    int xi = 0, ci = 1;
    if (in_sizes[0] == BATCH * NPTS) { xi = 1; ci = 0; }
    const float* X = (const float*)d_in[xi];
    const int*   C = (const int*)d_in[ci];
    float* out = (float*)d_out;

    prep_kernel<<<(BATCH * NPTS) / 256, 256>>>(X, C);

    cudaFuncSetAttribute(knn_kernel, cudaFuncAttributeMaxDynamicSharedMemorySize, SMEM_BYTES);
    knn_kernel<<<(BATCH * NPTS) / ROWS_PER_BLOCK, NTHREADS, SMEM_BYTES>>>(out);
}